// round 9
// baseline (speedup 1.0000x reference)
#include <cuda_runtime.h>
#include <cuda_bf16.h>
#include <cstdint>
#include <cstddef>

#define N_NODES 50000
#define C 128
#define E_EDGES 800000
#define SLOTS 64                                 // max stored degree (P(overflow)~1e-13)
#define BM 64                                    // GEMM rows per CTA
#define GEMM_BLOCKS ((N_NODES + BM - 1) / BM)    // 782

// Scratch (all __device__ globals — no allocation allowed)
__device__ float g_z[(size_t)N_NODES * C];       // z = (x @ W^T) * dinv[row]
__device__ int   g_cnt[N_NODES];                 // degree (atomic counters)
__device__ int   g_slot[(size_t)N_NODES * SLOTS];// neighbor cols, bucketed by row
__device__ int   g_stride;                       // 1 = int32 edge_index, 2 = int64

__device__ __forceinline__ float dinv_of(int deg) {
    return (deg > 0) ? rsqrtf((float)deg) : 0.0f;
}

// ---------------------------------------------------------------------------
// Fused: zero counters (all blocks) + dtype detection (block 0).
// int64 little-endian with values < 2^31 has all odd 32-bit words zero.
__global__ void zero_detect_kernel(const int* __restrict__ ei32) {
    int i = blockIdx.x * blockDim.x + threadIdx.x;
    if (i < N_NODES) g_cnt[i] = 0;
    if (blockIdx.x == 0) {
        __shared__ int any;
        if (threadIdx.x == 0) any = 0;
        __syncthreads();
        int nz = 0;
#pragma unroll
        for (int j = 0; j < 8; j++)
            nz |= ei32[(threadIdx.x + j * 256) * 2 + 1];
        if (nz != 0) atomicOr(&any, 1);
        __syncthreads();
        if (threadIdx.x == 0) g_stride = any ? 1 : 2;
    }
}

// One pass: count degree AND bucket the col into the row's slot array.
__global__ void fill_kernel(const int* __restrict__ ei32) {
    int i = blockIdx.x * blockDim.x + threadIdx.x;
    if (i < E_EDGES) {
        int stride = g_stride;
        int r = ei32[(size_t)i * stride];
        int c = ei32[((size_t)E_EDGES + i) * stride];
        if ((unsigned)r < N_NODES && (unsigned)c < N_NODES) {
            int pos = atomicAdd(&g_cnt[r], 1);
            if (pos < SLOTS) g_slot[(size_t)r * SLOTS + pos] = c;
        }
    }
}

// ---------------------------------------------------------------------------
// GEMM via mma.sync m16n8k16 bf16, 2-term split: Xhi*Whi + Xhi*Wlo + Xlo*Whi.
// Epilogue scales each output row by dinv[row]  ->  z = (X W^T) * dinv.
#define SM_WFH 0
#define SM_WFL 32768
#define SM_XFH 65536
#define SM_XFL 81920
#define SMEM_GEMM 98304

__device__ __forceinline__ void bf16_split2(float x, float y,
                                            uint32_t& h, uint32_t& l) {
    __nv_bfloat16 hx = __float2bfloat16(x), hy = __float2bfloat16(y);
    __nv_bfloat16 lx = __float2bfloat16(x - __bfloat162float(hx));
    __nv_bfloat16 ly = __float2bfloat16(y - __bfloat162float(hy));
    h = ((uint32_t)__bfloat16_as_ushort(hy) << 16) | __bfloat16_as_ushort(hx);
    l = ((uint32_t)__bfloat16_as_ushort(ly) << 16) | __bfloat16_as_ushort(lx);
}

#define MMA_BF16(c, a, b)                                                     \
    asm volatile(                                                             \
        "mma.sync.aligned.m16n8k16.row.col.f32.bf16.bf16.f32 "                \
        "{%0,%1,%2,%3}, {%4,%5,%6,%7}, {%8,%9}, {%0,%1,%2,%3};"               \
        : "+f"((c)[0]), "+f"((c)[1]), "+f"((c)[2]), "+f"((c)[3])              \
        : "r"((a).x), "r"((a).y), "r"((a).z), "r"((a).w),                     \
          "r"((b).x), "r"((b).y))

__global__ void __launch_bounds__(128) gemm_mma_kernel(
        const float* __restrict__ X, const float* __restrict__ W, int n) {
    extern __shared__ char smc[];
    uint32_t* sm32 = (uint32_t*)smc;
    const int tid = threadIdx.x;
    const int row0 = blockIdx.x * BM;

    for (int i = tid; i < 128 * 64; i += 128) {
        int r = i >> 6, p = i & 63;
        float2 v = *(const float2*)(W + (size_t)r * C + 2 * p);
        uint32_t h, l;
        bf16_split2(v.x, v.y, h, l);
        int kstep = p >> 3, t = p & 3, half = (p >> 2) & 1;
        int nt = r >> 3, g = r & 7, lane = g * 4 + t;
        int slot = ((kstep * 16 + nt) * 32 + lane) * 2 + half;
        sm32[(SM_WFH >> 2) + slot] = h;
        sm32[(SM_WFL >> 2) + slot] = l;
    }
    for (int i = tid; i < BM * 64; i += 128) {
        int r = i >> 6, p = i & 63;
        int gr = row0 + r;
        float2 v = make_float2(0.f, 0.f);
        if (gr < n) v = *(const float2*)(X + (size_t)gr * C + 2 * p);
        uint32_t h, l;
        bf16_split2(v.x, v.y, h, l);
        int w = r >> 4, g = r & 7, iidx = (r >> 3) & 1;
        int kstep = p >> 3, t = p & 3, ii = (p >> 2) & 1;
        int lane = g * 4 + t, reg = iidx + 2 * ii;
        int slot = ((w * 8 + kstep) * 32 + lane) * 4 + reg;
        sm32[(SM_XFH >> 2) + slot] = h;
        sm32[(SM_XFL >> 2) + slot] = l;
    }
    __syncthreads();

    const int lane = tid & 31, w = tid >> 5;
    float c[16][4];
#pragma unroll
    for (int nt = 0; nt < 16; nt++)
#pragma unroll
        for (int j = 0; j < 4; j++) c[nt][j] = 0.0f;

    const uint4* xfh = (const uint4*)(smc + SM_XFH) + (w * 8) * 32 + lane;
    const uint4* xfl = (const uint4*)(smc + SM_XFL) + (w * 8) * 32 + lane;
    const uint2* wfh = (const uint2*)(smc + SM_WFH) + lane;
    const uint2* wfl = (const uint2*)(smc + SM_WFL) + lane;

#pragma unroll
    for (int k = 0; k < 8; k++) {
        uint4 ah = xfh[k * 32];
        uint4 al = xfl[k * 32];
#pragma unroll
        for (int nt = 0; nt < 16; nt++) {
            uint2 bh = wfh[(k * 16 + nt) * 32];
            uint2 bl = wfl[(k * 16 + nt) * 32];
            MMA_BF16(c[nt], ah, bh);
            MMA_BF16(c[nt], ah, bl);
            MMA_BF16(c[nt], al, bh);
        }
    }

    // Epilogue: scale row by dinv[row], store z
    const int g = lane >> 2, t = lane & 3;
    const int rowA = row0 + w * 16 + g;
    const int rowB = rowA + 8;
    float dA = (rowA < n) ? dinv_of(__ldg(&g_cnt[rowA])) : 0.0f;
    float dB = (rowB < n) ? dinv_of(__ldg(&g_cnt[rowB])) : 0.0f;
#pragma unroll
    for (int nt = 0; nt < 16; nt++) {
        int col = nt * 8 + t * 2;
        if (rowA < n)
            *(float2*)(g_z + (size_t)rowA * C + col) =
                make_float2(c[nt][0] * dA, c[nt][1] * dA);
        if (rowB < n)
            *(float2*)(g_z + (size_t)rowB * C + col) =
                make_float2(c[nt][2] * dB, c[nt][3] * dB);
    }
}

// ---------------------------------------------------------------------------
// One warp per node, MLP=4, minimal inner loop:
//   out[n,:] = b + dinv[n] * sum_{c in nbrs(n)} z[c,:]
// Slots load as int4 (contiguous); z rows are pure float4 adds.
__global__ void agg_kernel(const float* __restrict__ b, float* __restrict__ out) {
    int node = (blockIdx.x * blockDim.x + threadIdx.x) >> 5;
    if (node >= N_NODES) return;
    const int lane = threadIdx.x & 31;

    int deg = __ldg(&g_cnt[node]);
    int end = (deg < SLOTS) ? deg : SLOTS;
    const int* slots = g_slot + (size_t)node * SLOTS;

    float4 acc0 = make_float4(0.f, 0.f, 0.f, 0.f);
    float4 acc1 = make_float4(0.f, 0.f, 0.f, 0.f);
    int s = 0;
    for (; s + 4 <= end; s += 4) {
        int4 cs = __ldg((const int4*)(slots + s));
        float4 v0 = ((const float4*)(g_z + (size_t)cs.x * C))[lane];
        float4 v1 = ((const float4*)(g_z + (size_t)cs.y * C))[lane];
        float4 v2 = ((const float4*)(g_z + (size_t)cs.z * C))[lane];
        float4 v3 = ((const float4*)(g_z + (size_t)cs.w * C))[lane];
        acc0.x += v0.x; acc1.x += v1.x;
        acc0.y += v0.y; acc1.y += v1.y;
        acc0.z += v0.z; acc1.z += v1.z;
        acc0.w += v0.w; acc1.w += v1.w;
        acc0.x += v2.x; acc1.x += v3.x;
        acc0.y += v2.y; acc1.y += v3.y;
        acc0.z += v2.z; acc1.z += v3.z;
        acc0.w += v2.w; acc1.w += v3.w;
    }
    for (; s < end; s++) {
        int c0 = __ldg(&slots[s]);
        float4 v0 = ((const float4*)(g_z + (size_t)c0 * C))[lane];
        acc0.x += v0.x; acc0.y += v0.y; acc0.z += v0.z; acc0.w += v0.w;
    }

    float dr = dinv_of(deg);
    float4 bias = ((const float4*)b)[lane];
    float4 o;
    o.x = fmaf(dr, acc0.x + acc1.x, bias.x);
    o.y = fmaf(dr, acc0.y + acc1.y, bias.y);
    o.z = fmaf(dr, acc0.z + acc1.z, bias.z);
    o.w = fmaf(dr, acc0.w + acc1.w, bias.w);
    ((float4*)(out + (size_t)node * C))[lane] = o;
}

extern "C" void kernel_launch(void* const* d_in, const int* in_sizes, int n_in,
                              void* d_out, int out_size) {
    const float* x   = (const float*)d_in[0];   // [50000,128]
    const int*   ei  = (const int*)d_in[1];     // [2,800000] int32 or int64
    const float* W   = (const float*)d_in[2];   // [128,128]
    const float* b   = (const float*)d_in[3];   // [128]
    float*       out = (float*)d_out;           // [50000,128]

    cudaFuncSetAttribute(gemm_mma_kernel,
                         cudaFuncAttributeMaxDynamicSharedMemorySize, SMEM_GEMM);

    zero_detect_kernel<<<(N_NODES + 255) / 256, 256>>>(ei);
    fill_kernel<<<(E_EDGES + 255) / 256, 256>>>(ei);
    gemm_mma_kernel<<<GEMM_BLOCKS, 128, SMEM_GEMM>>>(x, W, N_NODES);
    agg_kernel<<<(N_NODES * 32 + 255) / 256, 256>>>(b, out);
}

// round 10
// speedup vs baseline: 1.0793x; 1.0793x over previous
#include <cuda_runtime.h>
#include <cuda_bf16.h>
#include <cstdint>
#include <cstddef>

#define N_NODES 50000
#define C 128
#define E_EDGES 800000
#define SLOTS 64                                 // max stored degree (P(overflow)~1e-13)
#define BM 64                                    // GEMM rows per CTA
#define GEMM_BLOCKS ((N_NODES + BM - 1) / BM)    // 782

// Scratch (all __device__ globals — no allocation allowed)
__device__ float g_y[(size_t)N_NODES * C];       // y = x @ W^T (unscaled)
__device__ int   g_cnt[N_NODES];                 // degree (atomic counters)
__device__ float g_dinv[N_NODES];                // deg^-1/2 table
__device__ int   g_slot[(size_t)N_NODES * SLOTS];// neighbor cols, bucketed by row
__device__ int   g_stride;                       // 1 = int32 edge_index, 2 = int64

// ---------------------------------------------------------------------------
// Fused: zero counters (all blocks) + dtype detection (block 0).
// int64 little-endian with values < 2^31 has all odd 32-bit words zero.
__global__ void zero_detect_kernel(const int* __restrict__ ei32) {
    int i = blockIdx.x * blockDim.x + threadIdx.x;
    if (i < N_NODES) g_cnt[i] = 0;
    if (blockIdx.x == 0) {
        __shared__ int any;
        if (threadIdx.x == 0) any = 0;
        __syncthreads();
        int nz = 0;
#pragma unroll
        for (int j = 0; j < 8; j++)
            nz |= ei32[(threadIdx.x + j * 256) * 2 + 1];
        if (nz != 0) atomicOr(&any, 1);
        __syncthreads();
        if (threadIdx.x == 0) g_stride = any ? 1 : 2;
    }
}

// One pass: count degree AND bucket the col into the row's slot array.
__global__ void fill_kernel(const int* __restrict__ ei32) {
    int i = blockIdx.x * blockDim.x + threadIdx.x;
    if (i < E_EDGES) {
        int stride = g_stride;
        int r = ei32[(size_t)i * stride];
        int c = ei32[((size_t)E_EDGES + i) * stride];
        if ((unsigned)r < N_NODES && (unsigned)c < N_NODES) {
            int pos = atomicAdd(&g_cnt[r], 1);
            if (pos < SLOTS) g_slot[(size_t)r * SLOTS + pos] = c;
        }
    }
}

// dinv table from counters
__global__ void dinv_kernel() {
    int i = blockIdx.x * blockDim.x + threadIdx.x;
    if (i < N_NODES) {
        int d = g_cnt[i];
        g_dinv[i] = (d > 0) ? rsqrtf((float)d) : 0.0f;
    }
}

// ---------------------------------------------------------------------------
// GEMM via mma.sync m16n8k16 bf16, 2-term split: Xhi*Whi + Xhi*Wlo + Xlo*Whi.
// Depends ONLY on x and W -> runs on a forked stream concurrent with fill.
#define SM_WFH 0
#define SM_WFL 32768
#define SM_XFH 65536
#define SM_XFL 81920
#define SMEM_GEMM 98304

__device__ __forceinline__ void bf16_split2(float x, float y,
                                            uint32_t& h, uint32_t& l) {
    __nv_bfloat16 hx = __float2bfloat16(x), hy = __float2bfloat16(y);
    __nv_bfloat16 lx = __float2bfloat16(x - __bfloat162float(hx));
    __nv_bfloat16 ly = __float2bfloat16(y - __bfloat162float(hy));
    h = ((uint32_t)__bfloat16_as_ushort(hy) << 16) | __bfloat16_as_ushort(hx);
    l = ((uint32_t)__bfloat16_as_ushort(ly) << 16) | __bfloat16_as_ushort(lx);
}

#define MMA_BF16(c, a, b)                                                     \
    asm volatile(                                                             \
        "mma.sync.aligned.m16n8k16.row.col.f32.bf16.bf16.f32 "                \
        "{%0,%1,%2,%3}, {%4,%5,%6,%7}, {%8,%9}, {%0,%1,%2,%3};"               \
        : "+f"((c)[0]), "+f"((c)[1]), "+f"((c)[2]), "+f"((c)[3])              \
        : "r"((a).x), "r"((a).y), "r"((a).z), "r"((a).w),                     \
          "r"((b).x), "r"((b).y))

__global__ void __launch_bounds__(128) gemm_mma_kernel(
        const float* __restrict__ X, const float* __restrict__ W, int n) {
    extern __shared__ char smc[];
    uint32_t* sm32 = (uint32_t*)smc;
    const int tid = threadIdx.x;
    const int row0 = blockIdx.x * BM;

    for (int i = tid; i < 128 * 64; i += 128) {
        int r = i >> 6, p = i & 63;
        float2 v = *(const float2*)(W + (size_t)r * C + 2 * p);
        uint32_t h, l;
        bf16_split2(v.x, v.y, h, l);
        int kstep = p >> 3, t = p & 3, half = (p >> 2) & 1;
        int nt = r >> 3, g = r & 7, lane = g * 4 + t;
        int slot = ((kstep * 16 + nt) * 32 + lane) * 2 + half;
        sm32[(SM_WFH >> 2) + slot] = h;
        sm32[(SM_WFL >> 2) + slot] = l;
    }
    for (int i = tid; i < BM * 64; i += 128) {
        int r = i >> 6, p = i & 63;
        int gr = row0 + r;
        float2 v = make_float2(0.f, 0.f);
        if (gr < n) v = *(const float2*)(X + (size_t)gr * C + 2 * p);
        uint32_t h, l;
        bf16_split2(v.x, v.y, h, l);
        int w = r >> 4, g = r & 7, iidx = (r >> 3) & 1;
        int kstep = p >> 3, t = p & 3, ii = (p >> 2) & 1;
        int lane = g * 4 + t, reg = iidx + 2 * ii;
        int slot = ((w * 8 + kstep) * 32 + lane) * 4 + reg;
        sm32[(SM_XFH >> 2) + slot] = h;
        sm32[(SM_XFL >> 2) + slot] = l;
    }
    __syncthreads();

    const int lane = tid & 31, w = tid >> 5;
    float c[16][4];
#pragma unroll
    for (int nt = 0; nt < 16; nt++)
#pragma unroll
        for (int j = 0; j < 4; j++) c[nt][j] = 0.0f;

    const uint4* xfh = (const uint4*)(smc + SM_XFH) + (w * 8) * 32 + lane;
    const uint4* xfl = (const uint4*)(smc + SM_XFL) + (w * 8) * 32 + lane;
    const uint2* wfh = (const uint2*)(smc + SM_WFH) + lane;
    const uint2* wfl = (const uint2*)(smc + SM_WFL) + lane;

#pragma unroll
    for (int k = 0; k < 8; k++) {
        uint4 ah = xfh[k * 32];
        uint4 al = xfl[k * 32];
#pragma unroll
        for (int nt = 0; nt < 16; nt++) {
            uint2 bh = wfh[(k * 16 + nt) * 32];
            uint2 bl = wfl[(k * 16 + nt) * 32];
            MMA_BF16(c[nt], ah, bh);
            MMA_BF16(c[nt], ah, bl);
            MMA_BF16(c[nt], al, bh);
        }
    }

    const int g = lane >> 2, t = lane & 3;
    const int rowA = row0 + w * 16 + g;
    const int rowB = rowA + 8;
#pragma unroll
    for (int nt = 0; nt < 16; nt++) {
        int col = nt * 8 + t * 2;
        if (rowA < n)
            *(float2*)(g_y + (size_t)rowA * C + col) = make_float2(c[nt][0], c[nt][1]);
        if (rowB < n)
            *(float2*)(g_y + (size_t)rowB * C + col) = make_float2(c[nt][2], c[nt][3]);
    }
}

// ---------------------------------------------------------------------------
// One warp per node, MLP=4: int4 slot load + 4 uniform dinv loads + 4 y rows.
//   out[n,:] = b + dinv[n] * sum_c y[c,:]*dinv[c]
__global__ void agg_kernel(const float* __restrict__ b, float* __restrict__ out) {
    int node = (blockIdx.x * blockDim.x + threadIdx.x) >> 5;
    if (node >= N_NODES) return;
    const int lane = threadIdx.x & 31;

    int deg = __ldg(&g_cnt[node]);
    int end = (deg < SLOTS) ? deg : SLOTS;
    const int* slots = g_slot + (size_t)node * SLOTS;

    float4 acc0 = make_float4(0.f, 0.f, 0.f, 0.f);
    float4 acc1 = make_float4(0.f, 0.f, 0.f, 0.f);
    int s = 0;
    for (; s + 4 <= end; s += 4) {
        int4 cs = __ldg((const int4*)(slots + s));
        float d0 = __ldg(&g_dinv[cs.x]);
        float d1 = __ldg(&g_dinv[cs.y]);
        float d2 = __ldg(&g_dinv[cs.z]);
        float d3 = __ldg(&g_dinv[cs.w]);
        float4 v0 = ((const float4*)(g_y + (size_t)cs.x * C))[lane];
        float4 v1 = ((const float4*)(g_y + (size_t)cs.y * C))[lane];
        float4 v2 = ((const float4*)(g_y + (size_t)cs.z * C))[lane];
        float4 v3 = ((const float4*)(g_y + (size_t)cs.w * C))[lane];
        acc0.x = fmaf(v0.x, d0, acc0.x); acc1.x = fmaf(v1.x, d1, acc1.x);
        acc0.y = fmaf(v0.y, d0, acc0.y); acc1.y = fmaf(v1.y, d1, acc1.y);
        acc0.z = fmaf(v0.z, d0, acc0.z); acc1.z = fmaf(v1.z, d1, acc1.z);
        acc0.w = fmaf(v0.w, d0, acc0.w); acc1.w = fmaf(v1.w, d1, acc1.w);
        acc0.x = fmaf(v2.x, d2, acc0.x); acc1.x = fmaf(v3.x, d3, acc1.x);
        acc0.y = fmaf(v2.y, d2, acc0.y); acc1.y = fmaf(v3.y, d3, acc1.y);
        acc0.z = fmaf(v2.z, d2, acc0.z); acc1.z = fmaf(v3.z, d3, acc1.z);
        acc0.w = fmaf(v2.w, d2, acc0.w); acc1.w = fmaf(v3.w, d3, acc1.w);
    }
    for (; s < end; s++) {
        int c0 = __ldg(&slots[s]);
        float d0 = __ldg(&g_dinv[c0]);
        float4 v0 = ((const float4*)(g_y + (size_t)c0 * C))[lane];
        acc0.x = fmaf(v0.x, d0, acc0.x);
        acc0.y = fmaf(v0.y, d0, acc0.y);
        acc0.z = fmaf(v0.z, d0, acc0.z);
        acc0.w = fmaf(v0.w, d0, acc0.w);
    }

    float dr = __ldg(&g_dinv[node]);
    float4 bias = ((const float4*)b)[lane];
    float4 o;
    o.x = fmaf(dr, acc0.x + acc1.x, bias.x);
    o.y = fmaf(dr, acc0.y + acc1.y, bias.y);
    o.z = fmaf(dr, acc0.z + acc1.z, bias.z);
    o.w = fmaf(dr, acc0.w + acc1.w, bias.w);
    ((float4*)(out + (size_t)node * C))[lane] = o;
}

extern "C" void kernel_launch(void* const* d_in, const int* in_sizes, int n_in,
                              void* d_out, int out_size) {
    const float* x   = (const float*)d_in[0];   // [50000,128]
    const int*   ei  = (const int*)d_in[1];     // [2,800000] int32 or int64
    const float* W   = (const float*)d_in[2];   // [128,128]
    const float* b   = (const float*)d_in[3];   // [128]
    float*       out = (float*)d_out;           // [50000,128]

    cudaFuncSetAttribute(gemm_mma_kernel,
                         cudaFuncAttributeMaxDynamicSharedMemorySize, SMEM_GEMM);

    // Fork-join: GEMM (x,W only) runs concurrent with the edge pipeline.
    cudaStream_t s2;
    cudaStreamCreateWithFlags(&s2, cudaStreamNonBlocking);
    cudaEvent_t ev_fork, ev_join;
    cudaEventCreateWithFlags(&ev_fork, cudaEventDisableTiming);
    cudaEventCreateWithFlags(&ev_join, cudaEventDisableTiming);

    cudaEventRecord(ev_fork, 0);
    cudaStreamWaitEvent(s2, ev_fork, 0);
    gemm_mma_kernel<<<GEMM_BLOCKS, 128, SMEM_GEMM, s2>>>(x, W, N_NODES);
    cudaEventRecord(ev_join, s2);

    zero_detect_kernel<<<(N_NODES + 255) / 256, 256>>>(ei);
    fill_kernel<<<(E_EDGES + 255) / 256, 256>>>(ei);
    dinv_kernel<<<(N_NODES + 255) / 256, 256>>>();

    cudaStreamWaitEvent(0, ev_join, 0);
    agg_kernel<<<(N_NODES * 32 + 255) / 256, 256>>>(b, out);

    cudaEventDestroy(ev_fork);
    cudaEventDestroy(ev_join);
    cudaStreamDestroy(s2);
}